// round 1
// baseline (speedup 1.0000x reference)
#include <cuda_runtime.h>
#include <cuda_bf16.h>
#include <math.h>

// Inter-layer scratch (allocation-free rule: __device__ globals).
__device__ float g_out0[729];
__device__ float g_out1[27];

#define PI_HALF 1.57079632679489662f

__device__ __forceinline__ float warp_sum(float v) {
#pragma unroll
    for (int o = 16; o > 0; o >>= 1)
        v += __shfl_down_sync(0xffffffffu, v, o);
    return v;
}

// One warp contracts one scalar-output MPS chain (O=1, D=32, 27 sites).
// first: 64 floats  [p][0][d]
// mid:   25*2048 floats [m][d][p][e]
// last:  64 floats  [d][p]
// sc/ss: cos/sin embeddings for the 27 sites (in smem)
// vbuf:  32-float smem bond vector
__device__ __forceinline__ float mps_scalar_chain(
    const float* __restrict__ first, const float* __restrict__ mid,
    const float* __restrict__ last, const float* sc, const float* ss,
    float* vbuf, int t)
{
    // v0[d] = first[0,0,d]*cos0 + first[1,0,d]*sin0
    float v = fmaf(first[t], sc[0], first[32 + t] * ss[0]);
    vbuf[t] = v;
    __syncwarp();

    for (int m = 0; m < 25; m++) {
        const float* __restrict__ A = mid + m * 2048;
        const float c = sc[m + 1];
        const float s = ss[m + 1];
        float acc = 0.0f;
        // v_new[t] = sum_d v[d] * (A[d,0,t]*c + A[d,1,t]*s)
        // 64 independent coalesced LDGs per step -> high MLP.
#pragma unroll
        for (int d = 0; d < 32; d++) {
            const float w = vbuf[d];
            const float mval = fmaf(A[d * 64 + t], c, A[d * 64 + 32 + t] * s);
            acc = fmaf(w, mval, acc);
        }
        __syncwarp();           // all reads of vbuf done
        vbuf[t] = acc;
        __syncwarp();
    }

    const float c = sc[26], s = ss[26];
    const float part = vbuf[t] * fmaf(last[2 * t], c, last[2 * t + 1] * s);
    return warp_sum(part);
}

// ---------------- Layer 0: 729 chains over the 27^3 input image ----------------
__global__ void __launch_bounds__(32)
layer0_kernel(const float* __restrict__ img,
              const float* __restrict__ first,
              const float* __restrict__ mid,
              const float* __restrict__ last)
{
    __shared__ float sc[27], ss[27], vbuf[32];
    const int n = blockIdx.x;
    const int t = threadIdx.x;
    const int bh = n / 81, bv = (n / 9) % 9, bd = n % 9;

    if (t < 27) {
        const int x = t / 9, y = (t / 3) % 3, z = t % 3;
        const float val = img[(3 * bh + x) * 729 + (3 * bv + y) * 27 + (3 * bd + z)];
        float cv, sv;
        sincosf(PI_HALF * val, &sv, &cv);
        sc[t] = cv; ss[t] = sv;
    }
    __syncwarp();

    const float r = mps_scalar_chain(first + n * 64, mid + (long)n * 51200,
                                     last + n * 64, sc, ss, vbuf, t);
    if (t == 0) g_out0[n] = r;
}

// ---------------- Layer 1: 27 chains over the (9,9,9) intermediate ----------------
__global__ void __launch_bounds__(32)
layer1_kernel(const float* __restrict__ first,
              const float* __restrict__ mid,
              const float* __restrict__ last)
{
    __shared__ float sc[27], ss[27], vbuf[32];
    const int n = blockIdx.x;
    const int t = threadIdx.x;
    const int bh = n / 9, bv = (n / 3) % 3, bd = n % 3;

    if (t < 27) {
        const int x = t / 9, y = (t / 3) % 3, z = t % 3;
        const float val = g_out0[(3 * bh + x) * 81 + (3 * bv + y) * 9 + (3 * bd + z)];
        float cv, sv;
        sincosf(PI_HALF * val, &sv, &cv);
        sc[t] = cv; ss[t] = sv;
    }
    __syncwarp();

    const float r = mps_scalar_chain(first + n * 64, mid + n * 51200,
                                     last + n * 64, sc, ss, vbuf, t);
    if (t == 0) g_out1[n] = r;
}

// ---------------- Final layer: one chain with output leg O=10 ----------------
__global__ void __launch_bounds__(32)
final_kernel(const float* __restrict__ ffirst,   // (2,10,32) [p][o][d]
             const float* __restrict__ fmid,     // (25,32,2,32)
             const float* __restrict__ flast,    // (32,2)
             float* __restrict__ out)            // (10,)
{
    __shared__ float sc[27], ss[27];
    __shared__ float vbuf[10][32];
    const int t = threadIdx.x;

    if (t < 27) {
        // (3,3,3) squeeze of g_out1 is the identity permutation: feature f = flat index
        float cv, sv;
        sincosf(PI_HALF * g_out1[t], &sv, &cv);
        sc[t] = cv; ss[t] = sv;
    }
    __syncwarp();

    float v[10];
#pragma unroll
    for (int o = 0; o < 10; o++) {
        v[o] = fmaf(ffirst[o * 32 + t], sc[0], ffirst[320 + o * 32 + t] * ss[0]);
        vbuf[o][t] = v[o];
    }
    __syncwarp();

    for (int m = 0; m < 25; m++) {
        const float* __restrict__ A = fmid + m * 2048;
        const float c = sc[m + 1];
        const float s = ss[m + 1];
        float Mcol[32];
#pragma unroll
        for (int d = 0; d < 32; d++)
            Mcol[d] = fmaf(A[d * 64 + t], c, A[d * 64 + 32 + t] * s);
#pragma unroll
        for (int o = 0; o < 10; o++) {
            float acc = 0.0f;
#pragma unroll
            for (int d = 0; d < 32; d++)
                acc = fmaf(vbuf[o][d], Mcol[d], acc);
            v[o] = acc;
        }
        __syncwarp();
#pragma unroll
        for (int o = 0; o < 10; o++) vbuf[o][t] = v[o];
        __syncwarp();
    }

    const float c = sc[26], s = ss[26];
    const float w = fmaf(flast[2 * t], c, flast[2 * t + 1] * s);
#pragma unroll
    for (int o = 0; o < 10; o++) {
        const float r = warp_sum(v[o] * w);
        if (t == 0) out[o] = r;
    }
}

extern "C" void kernel_launch(void* const* d_in, const int* in_sizes, int n_in,
                              void* d_out, int out_size)
{
    const float* img      = (const float*)d_in[0];
    const float* l0_first = (const float*)d_in[1];
    const float* l0_mid   = (const float*)d_in[2];
    const float* l0_last  = (const float*)d_in[3];
    const float* l1_first = (const float*)d_in[4];
    const float* l1_mid   = (const float*)d_in[5];
    const float* l1_last  = (const float*)d_in[6];
    const float* f_first  = (const float*)d_in[7];
    const float* f_mid    = (const float*)d_in[8];
    const float* f_last   = (const float*)d_in[9];
    float* out = (float*)d_out;

    layer0_kernel<<<729, 32>>>(img, l0_first, l0_mid, l0_last);
    layer1_kernel<<<27, 32>>>(l1_first, l1_mid, l1_last);
    final_kernel<<<1, 32>>>(f_first, f_mid, f_last, out);
}

// round 2
// speedup vs baseline: 1.7891x; 1.7891x over previous
#include <cuda_runtime.h>
#include <cuda_bf16.h>
#include <math.h>
#include <stdint.h>

// Inter-layer scratch (allocation-free rule: __device__ globals).
__device__ float g_out0[729];
__device__ float g_out1[27];

#define PI_HALF 1.57079632679489662f
#define STAGES 25
#define STAGE_FLOATS 2048
#define STAGE_BYTES 8192
#define SMEM_DYN_BYTES (STAGES * STAGE_BYTES)   // 204800 B

// ---------------- PTX helpers (inline, sm_90+/sm_103a) ----------------
__device__ __forceinline__ uint32_t smem_u32(const void* p) {
    return (uint32_t)__cvta_generic_to_shared(p);
}
__device__ __forceinline__ void mbar_init(uint32_t bar, uint32_t cnt) {
    asm volatile("mbarrier.init.shared.b64 [%0], %1;" :: "r"(bar), "r"(cnt) : "memory");
}
__device__ __forceinline__ void fence_proxy_async_smem() {
    asm volatile("fence.proxy.async.shared::cta;" ::: "memory");
}
__device__ __forceinline__ void mbar_expect_tx(uint32_t bar, uint32_t bytes) {
    asm volatile("mbarrier.arrive.expect_tx.shared.b64 _, [%0], %1;"
                 :: "r"(bar), "r"(bytes) : "memory");
}
__device__ __forceinline__ void tma_bulk_g2s(uint32_t dst, const void* src,
                                             uint32_t bytes, uint32_t bar) {
    asm volatile(
        "cp.async.bulk.shared::cluster.global.mbarrier::complete_tx::bytes "
        "[%0], [%1], %2, [%3];"
        :: "r"(dst), "l"(src), "r"(bytes), "r"(bar) : "memory");
}
__device__ __forceinline__ void mbar_wait_parity0(uint32_t bar) {
    asm volatile(
        "{\n\t"
        ".reg .pred P;\n\t"
        "WAIT_LOOP_%=:\n\t"
        "mbarrier.try_wait.parity.acquire.cta.shared::cta.b64 P, [%0], 0, 0x989680;\n\t"
        "@P bra.uni WAIT_DONE_%=;\n\t"
        "bra.uni WAIT_LOOP_%=;\n\t"
        "WAIT_DONE_%=:\n\t"
        "}"
        :: "r"(bar) : "memory");
}
__device__ __forceinline__ float warp_sum(float v) {
#pragma unroll
    for (int o = 16; o > 0; o >>= 1)
        v += __shfl_down_sync(0xffffffffu, v, o);
    return v;
}

// ---------------- Chain kernel (layers 0 and 1) ----------------
// One block per chain, 64 threads (2 warps split the d-reduction).
// All 25 step matrices are TMA-bulk-prefetched into shared memory.
__global__ void __launch_bounds__(64)
chain_kernel(const float* __restrict__ src,  // image or previous layer output
             int s, int st0, int st1,        // squeeze dims/strides
             const float* __restrict__ first,
             const float* __restrict__ mid,
             const float* __restrict__ last,
             float* __restrict__ out)
{
    extern __shared__ float smem[];              // 25 stages x 2048 floats
    __shared__ float sc[27], ss[27], vbuf[32], part[32];
    __shared__ __align__(8) unsigned long long bars[STAGES];

    const int n = blockIdx.x;
    const int t = threadIdx.x;
    const float* __restrict__ midn = mid + (long)n * (STAGES * STAGE_FLOATS);
    const float* __restrict__ fstn = first + n * 64;
    const float* __restrict__ lstn = last + n * 64;

    // Producer: init barriers, then issue all 25 bulk copies up front.
    if (t == 0) {
#pragma unroll
        for (int m = 0; m < STAGES; m++) mbar_init(smem_u32(&bars[m]), 1);
        fence_proxy_async_smem();
        const uint32_t sbase = smem_u32(smem);
#pragma unroll 1
        for (int m = 0; m < STAGES; m++) {
            const uint32_t bar = smem_u32(&bars[m]);
            mbar_expect_tx(bar, STAGE_BYTES);
            tma_bulk_g2s(sbase + m * STAGE_BYTES, midn + m * STAGE_FLOATS,
                         STAGE_BYTES, bar);
        }
    }

    // Trig embedding of the 27 squeezed sites.
    if (t < 27) {
        const int bh = n / (s * s), bv = (n / s) % s, bd = n % s;
        const int x = t / 9, y = (t / 3) % 3, z = t % 3;
        const float val = src[(3 * bh + x) * st0 + (3 * bv + y) * st1 + (3 * bd + z)];
        float cv, sv;
        sincosf(PI_HALF * val, &sv, &cv);
        sc[t] = cv; ss[t] = sv;
    }
    __syncthreads();
    if (t < 32)
        vbuf[t] = fmaf(fstn[t], sc[0], fstn[32 + t] * ss[0]);
    __syncthreads();

    const int w = t >> 5;          // warp id: 0 or 1
    const int l = t & 31;          // lane = output bond index e
    const int d0 = w * 16;         // this warp's d half

#pragma unroll 1
    for (int m = 0; m < STAGES; m++) {
        mbar_wait_parity0(smem_u32(&bars[m]));
        const float* __restrict__ A = smem + m * STAGE_FLOATS;
        const float c = sc[m + 1], sn = ss[m + 1];
        float acc = 0.0f;
#pragma unroll
        for (int dd = 0; dd < 16; dd++) {
            const int d = d0 + dd;
            // conflict-free: word (d*64 + l) % 32 == l
            acc = fmaf(vbuf[d], fmaf(A[d * 64 + l], c, A[d * 64 + 32 + l] * sn), acc);
        }
        if (w == 1) part[l] = acc;
        __syncthreads();
        if (w == 0) vbuf[l] = acc + part[l];
        __syncthreads();
    }

    if (t < 32) {
        float pv = vbuf[t] * fmaf(lstn[2 * t], sc[26], lstn[2 * t + 1] * ss[26]);
        pv = warp_sum(pv);
        if (t == 0) out[n] = pv;
    }
}

// ---------------- Final layer: one chain with output leg O=10 ----------------
// Contract RIGHT-to-LEFT so the carried state is a plain 32-vector; the
// 10-way output leg appears only in the terminal dot product with site 0.
__global__ void __launch_bounds__(32)
final_kernel(const float* __restrict__ ffirst,   // (2,10,32) [p][o][d]
             const float* __restrict__ fmid,     // (25,32,2,32)
             const float* __restrict__ flast,    // (32,2)
             float* __restrict__ out)            // (10,)
{
    extern __shared__ float smem[];
    __shared__ float sc[27], ss[27], u[32];
    __shared__ __align__(8) unsigned long long bars[STAGES];

    const int t = threadIdx.x;

    if (t == 0) {
#pragma unroll
        for (int m = 0; m < STAGES; m++) mbar_init(smem_u32(&bars[m]), 1);
        fence_proxy_async_smem();
        const uint32_t sbase = smem_u32(smem);
        // Issue in consumption (reverse) order.
#pragma unroll 1
        for (int m = STAGES - 1; m >= 0; m--) {
            const uint32_t bar = smem_u32(&bars[m]);
            mbar_expect_tx(bar, STAGE_BYTES);
            tma_bulk_g2s(sbase + m * STAGE_BYTES, fmid + m * STAGE_FLOATS,
                         STAGE_BYTES, bar);
        }
    }

    if (t < 27) {
        // (3,3,3) squeeze of g_out1 is the identity permutation.
        float cv, sv;
        sincosf(PI_HALF * g_out1[t], &sv, &cv);
        sc[t] = cv; ss[t] = sv;
    }
    __syncwarp();

    // u_25[d] = last[d,0]*c26 + last[d,1]*s26
    u[t] = fmaf(flast[2 * t], sc[26], flast[2 * t + 1] * ss[26]);
    __syncwarp();

#pragma unroll 1
    for (int m = STAGES - 1; m >= 0; m--) {
        mbar_wait_parity0(smem_u32(&bars[m]));
        const float* __restrict__ A = smem + m * STAGE_FLOATS;
        const float c = sc[m + 1], sn = ss[m + 1];
        float a0 = 0.0f, a1 = 0.0f;
        // u_new[t] = c * (A[t,0,:]·u) + s * (A[t,1,:]·u)
        // rotated index (k+t)&31 keeps both LDS streams conflict-free.
#pragma unroll
        for (int k = 0; k < 32; k++) {
            const int e = (k + t) & 31;
            const float ue = u[e];
            a0 = fmaf(A[t * 64 + e], ue, a0);
            a1 = fmaf(A[t * 64 + 32 + e], ue, a1);
        }
        const float un = fmaf(a0, c, a1 * sn);
        __syncwarp();
        u[t] = un;
        __syncwarp();
    }

    const float ut = u[t];
#pragma unroll
    for (int o = 0; o < 10; o++) {
        float p = fmaf(ffirst[o * 32 + t], sc[0], ffirst[320 + o * 32 + t] * ss[0]) * ut;
        p = warp_sum(p);
        if (t == 0) out[o] = p;
    }
}

extern "C" void kernel_launch(void* const* d_in, const int* in_sizes, int n_in,
                              void* d_out, int out_size)
{
    const float* img      = (const float*)d_in[0];
    const float* l0_first = (const float*)d_in[1];
    const float* l0_mid   = (const float*)d_in[2];
    const float* l0_last  = (const float*)d_in[3];
    const float* l1_first = (const float*)d_in[4];
    const float* l1_mid   = (const float*)d_in[5];
    const float* l1_last  = (const float*)d_in[6];
    const float* f_first  = (const float*)d_in[7];
    const float* f_mid    = (const float*)d_in[8];
    const float* f_last   = (const float*)d_in[9];
    float* out = (float*)d_out;

    cudaFuncSetAttribute(chain_kernel,
                         cudaFuncAttributeMaxDynamicSharedMemorySize, SMEM_DYN_BYTES);
    cudaFuncSetAttribute(final_kernel,
                         cudaFuncAttributeMaxDynamicSharedMemorySize, SMEM_DYN_BYTES);

    float *p0 = nullptr, *p1 = nullptr;
    cudaGetSymbolAddress((void**)&p0, g_out0);
    cudaGetSymbolAddress((void**)&p1, g_out1);

    // Layer 0: 729 chains over the 27^3 image
    chain_kernel<<<729, 64, SMEM_DYN_BYTES>>>(img, 9, 729, 27,
                                              l0_first, l0_mid, l0_last, p0);
    // Layer 1: 27 chains over the (9,9,9) intermediate
    chain_kernel<<<27, 64, SMEM_DYN_BYTES>>>(p0, 3, 81, 9,
                                             l1_first, l1_mid, l1_last, p1);
    // Final layer
    final_kernel<<<1, 32, SMEM_DYN_BYTES>>>(f_first, f_mid, f_last, out);
}

// round 3
// speedup vs baseline: 2.5009x; 1.3978x over previous
#include <cuda_runtime.h>
#include <cuda_bf16.h>
#include <math.h>
#include <stdint.h>

// Inter-layer scratch + sync counters (allocation-free rule: __device__ globals).
__device__ float g_out0[729];
__device__ float g_out1[27];
__device__ unsigned g_ctrs[2];

#define PI_HALF 1.57079632679489662f
#define DEPTH 4
#define STAGE_FLOATS 2048
#define STAGE_BYTES 8192
#define SMEM_DYN (DEPTH * STAGE_BYTES)   // 32 KB -> ~6 CTAs/SM, all 729 resident

// ---------------- PTX helpers ----------------
__device__ __forceinline__ uint32_t smem_u32(const void* p) {
    return (uint32_t)__cvta_generic_to_shared(p);
}
__device__ __forceinline__ void mbar_init(uint32_t bar, uint32_t cnt) {
    asm volatile("mbarrier.init.shared.b64 [%0], %1;" :: "r"(bar), "r"(cnt) : "memory");
}
__device__ __forceinline__ void fence_proxy_async_smem() {
    asm volatile("fence.proxy.async.shared::cta;" ::: "memory");
}
__device__ __forceinline__ void mbar_expect_tx(uint32_t bar, uint32_t bytes) {
    asm volatile("mbarrier.arrive.expect_tx.shared.b64 _, [%0], %1;"
                 :: "r"(bar), "r"(bytes) : "memory");
}
__device__ __forceinline__ void tma_bulk_g2s(uint32_t dst, const void* src,
                                             uint32_t bytes, uint32_t bar) {
    asm volatile(
        "cp.async.bulk.shared::cluster.global.mbarrier::complete_tx::bytes "
        "[%0], [%1], %2, [%3];"
        :: "r"(dst), "l"(src), "r"(bytes), "r"(bar) : "memory");
}
__device__ __forceinline__ void mbar_wait(uint32_t bar, uint32_t parity) {
    asm volatile(
        "{\n\t"
        ".reg .pred P;\n\t"
        "WAIT_LOOP_%=:\n\t"
        "mbarrier.try_wait.parity.acquire.cta.shared::cta.b64 P, [%0], %1, 0x989680;\n\t"
        "@P bra.uni WAIT_DONE_%=;\n\t"
        "bra.uni WAIT_LOOP_%=;\n\t"
        "WAIT_DONE_%=:\n\t"
        "}"
        :: "r"(bar), "r"(parity) : "memory");
}
__device__ __forceinline__ float warp_sum(float v) {
#pragma unroll
    for (int o = 16; o > 0; o >>= 1)
        v += __shfl_down_sync(0xffffffffu, v, o);
    return v;
}
__device__ __forceinline__ void issue_stage(uint32_t sbase, uint32_t barsb,
                                            const float* g, int stage, int slot) {
    const uint32_t bar = barsb + slot * 8;
    mbar_expect_tx(bar, STAGE_BYTES);
    tma_bulk_g2s(sbase + slot * STAGE_BYTES, g + stage * STAGE_FLOATS,
                 STAGE_BYTES, bar);
}
__device__ __forceinline__ void spin_until(const unsigned* c, unsigned target) {
    unsigned v;
    do {
        asm volatile("ld.global.acquire.gpu.u32 %0, [%1];"
                     : "=r"(v) : "l"(c) : "memory");
        if (v >= target) return;
        __nanosleep(128);
    } while (true);
}

// Forward scalar MPS chain on one warp, TMA ring-buffered.
// Prologue (stages 0..3) must have been issued by lane 0 before the call.
__device__ __forceinline__ float chain_fwd(
    const float* __restrict__ gmid, const float* __restrict__ first,
    const float* __restrict__ last, const float* sc, const float* ss,
    float* vbuf, const float* stg, uint32_t sbase, uint32_t barsb,
    uint32_t& par, int t)
{
    vbuf[t] = fmaf(first[t], sc[0], first[32 + t] * ss[0]);
    __syncwarp();

#pragma unroll 1
    for (int m = 0; m < 25; m++) {
        const int slot = m & 3;
        mbar_wait(barsb + slot * 8, (par >> slot) & 1u);
        par ^= 1u << slot;
        const float* __restrict__ A = stg + slot * STAGE_FLOATS;
        const float c = sc[m + 1], sn = ss[m + 1];
        float acc = 0.0f;
#pragma unroll
        for (int d = 0; d < 32; d++)
            acc = fmaf(vbuf[d], fmaf(A[d * 64 + t], c, A[d * 64 + 32 + t] * sn), acc);
        __syncwarp();                     // all lanes done reading slot + vbuf
        if (t == 0 && m + DEPTH < 25)
            issue_stage(sbase, barsb, gmid, m + DEPTH, slot);
        vbuf[t] = acc;
        __syncwarp();
    }
    const float pv = vbuf[t] * fmaf(last[2 * t], sc[26], last[2 * t + 1] * ss[26]);
    return warp_sum(pv);
}

__global__ void reset_kernel() { g_ctrs[0] = 0; g_ctrs[1] = 0; }

// One persistent fused kernel: 729 blocks x 32 threads.
// Blocks 0-26 additionally do layer 1; block 0 additionally does the final layer.
__global__ void __launch_bounds__(32)
fused_kernel(const float* __restrict__ img,
             const float* __restrict__ l0f, const float* __restrict__ l0m,
             const float* __restrict__ l0l,
             const float* __restrict__ l1f, const float* __restrict__ l1m,
             const float* __restrict__ l1l,
             const float* __restrict__ ff,  const float* __restrict__ fm,
             const float* __restrict__ fl,
             float* __restrict__ out)
{
    extern __shared__ float stg[];                       // DEPTH x 2048 floats
    __shared__ float sc[27], ss[27], vbuf[32];
    __shared__ __align__(8) unsigned long long bars[DEPTH];

    const int n = blockIdx.x;
    const int t = threadIdx.x;
    const uint32_t sbase = smem_u32(stg);
    const uint32_t barsb = smem_u32(bars);
    uint32_t par = 0;                                     // per-slot phase parity bits

    if (t == 0) {
#pragma unroll
        for (int s = 0; s < DEPTH; s++) mbar_init(barsb + s * 8, 1);
        fence_proxy_async_smem();
    }
    __syncwarp();

    // ---------- Layer 0 ----------
    const float* gm0 = l0m + (long)n * (25 * STAGE_FLOATS);
    if (t == 0) {
#pragma unroll
        for (int s = 0; s < DEPTH; s++) issue_stage(sbase, barsb, gm0, s, s);
    }
    if (t < 27) {
        const int bh = n / 81, bv = (n / 9) % 9, bd = n % 9;
        const int x = t / 9, y = (t / 3) % 3, z = t % 3;
        const float val = img[(3 * bh + x) * 729 + (3 * bv + y) * 27 + (3 * bd + z)];
        float cv, sv;
        sincosf(PI_HALF * val, &sv, &cv);
        sc[t] = cv; ss[t] = sv;
    }
    __syncwarp();

    float r = chain_fwd(gm0, l0f + n * 64, l0l + n * 64, sc, ss,
                        vbuf, stg, sbase, barsb, par, t);
    if (t == 0) {
        g_out0[n] = r;
        __threadfence();
        atomicAdd(&g_ctrs[0], 1u);
    }
    if (n >= 27) return;

    // ---------- Layer 1 (blocks 0..26) ----------
    const float* gm1 = l1m + n * (25 * STAGE_FLOATS);
    if (t == 0) {                                 // prefetch weights BEFORE spinning
#pragma unroll
        for (int s = 0; s < DEPTH; s++) issue_stage(sbase, barsb, gm1, s, s);
    }
    spin_until(&g_ctrs[0], 729u);                 // all lanes poll (broadcast load)

    if (t < 27) {
        const int bh = n / 9, bv = (n / 3) % 3, bd = n % 3;
        const int x = t / 9, y = (t / 3) % 3, z = t % 3;
        const float val = __ldcg(&g_out0[(3 * bh + x) * 81 + (3 * bv + y) * 9 + (3 * bd + z)]);
        float cv, sv;
        sincosf(PI_HALF * val, &sv, &cv);
        sc[t] = cv; ss[t] = sv;
    }
    __syncwarp();

    r = chain_fwd(gm1, l1f + n * 64, l1l + n * 64, sc, ss,
                  vbuf, stg, sbase, barsb, par, t);
    if (t == 0) {
        g_out1[n] = r;
        __threadfence();
        atomicAdd(&g_ctrs[1], 1u);
    }
    if (n != 0) return;

    // ---------- Final layer (block 0): right-to-left, output leg at the end ----------
    if (t == 0) {                                 // reverse-order prefetch before spin
#pragma unroll
        for (int j = 0; j < DEPTH; j++) issue_stage(sbase, barsb, fm, 24 - j, j);
    }
    spin_until(&g_ctrs[1], 27u);

    if (t < 27) {
        // (3,3,3) squeeze of g_out1 is the identity permutation
        float cv, sv;
        sincosf(PI_HALF * __ldcg(&g_out1[t]), &sv, &cv);
        sc[t] = cv; ss[t] = sv;
    }
    __syncwarp();

    // u_25[d] = last[d,0]*c26 + last[d,1]*s26
    vbuf[t] = fmaf(fl[2 * t], sc[26], fl[2 * t + 1] * ss[26]);
    __syncwarp();

#pragma unroll 1
    for (int j = 0; j < 25; j++) {
        const int slot = j & 3;
        const int stage = 24 - j;
        mbar_wait(barsb + slot * 8, (par >> slot) & 1u);
        par ^= 1u << slot;
        const float* __restrict__ A = stg + slot * STAGE_FLOATS;
        const float c = sc[stage + 1], sn = ss[stage + 1];
        float a0 = 0.0f, a1 = 0.0f;
        // u_new[t] = c*(A[t,0,:]·u) + s*(A[t,1,:]·u); rotated e keeps LDS conflict-free
#pragma unroll
        for (int k = 0; k < 32; k++) {
            const int e = (k + t) & 31;
            const float ue = vbuf[e];
            a0 = fmaf(A[t * 64 + e], ue, a0);
            a1 = fmaf(A[t * 64 + 32 + e], ue, a1);
        }
        const float un = fmaf(a0, c, a1 * sn);
        __syncwarp();
        if (t == 0 && j + DEPTH < 25)
            issue_stage(sbase, barsb, fm, stage - DEPTH, slot);
        vbuf[t] = un;
        __syncwarp();
    }

    const float ut = vbuf[t];
#pragma unroll
    for (int o = 0; o < 10; o++) {
        float p = fmaf(ff[o * 32 + t], sc[0], ff[320 + o * 32 + t] * ss[0]) * ut;
        p = warp_sum(p);
        if (t == 0) out[o] = p;
    }
}

extern "C" void kernel_launch(void* const* d_in, const int* in_sizes, int n_in,
                              void* d_out, int out_size)
{
    const float* img      = (const float*)d_in[0];
    const float* l0_first = (const float*)d_in[1];
    const float* l0_mid   = (const float*)d_in[2];
    const float* l0_last  = (const float*)d_in[3];
    const float* l1_first = (const float*)d_in[4];
    const float* l1_mid   = (const float*)d_in[5];
    const float* l1_last  = (const float*)d_in[6];
    const float* f_first  = (const float*)d_in[7];
    const float* f_mid    = (const float*)d_in[8];
    const float* f_last   = (const float*)d_in[9];
    float* out = (float*)d_out;

    reset_kernel<<<1, 1>>>();
    fused_kernel<<<729, 32, SMEM_DYN>>>(img, l0_first, l0_mid, l0_last,
                                        l1_first, l1_mid, l1_last,
                                        f_first, f_mid, f_last, out);
}

// round 4
// speedup vs baseline: 2.6750x; 1.0696x over previous
#include <cuda_runtime.h>
#include <cuda_bf16.h>
#include <math.h>
#include <stdint.h>

// Inter-layer scratch + sync (allocation-free rule: __device__ globals).
__device__ float g_out0[729];
__device__ float g_out1[27];
__device__ unsigned g_grp[27];   // per-layer1-chain producer counters (27 each)
__device__ unsigned g_ctr1;      // layer1 completion counter

#define PI_HALF 1.57079632679489662f
#define DEPTH 5
#define STAGE_FLOATS 2048
#define STAGE_BYTES 8192
#define SMEM_DYN (DEPTH * STAGE_BYTES)   // 40 KB -> 5 CTAs/SM, all 729 resident

// ---------------- helpers ----------------
__device__ __forceinline__ uint32_t smem_u32(const void* p) {
    return (uint32_t)__cvta_generic_to_shared(p);
}
__device__ __forceinline__ void cpa16(uint32_t d, const float* s) {
    asm volatile("cp.async.cg.shared.global [%0], [%1], 16;" :: "r"(d), "l"(s) : "memory");
}
__device__ __forceinline__ void cp_commit() {
    asm volatile("cp.async.commit_group;" ::: "memory");
}
__device__ __forceinline__ void cp_wait4() {
    asm volatile("cp.async.wait_group 4;" ::: "memory");
}
__device__ __forceinline__ void l2_prefetch_line(const float* p) {
    asm volatile("prefetch.global.L2 [%0];" :: "l"(p));
}
__device__ __forceinline__ float warp_sum(float v) {
#pragma unroll
    for (int o = 16; o > 0; o >>= 1)
        v += __shfl_down_sync(0xffffffffu, v, o);
    return v;
}
__device__ __forceinline__ void spin_until(const unsigned* c, unsigned target) {
    unsigned v;
    do {
        asm volatile("ld.global.acquire.gpu.u32 %0, [%1];"
                     : "=r"(v) : "l"(c) : "memory");
        if (v >= target) return;
        __nanosleep(128);
    } while (true);
}

// Warp-wide issue of one 8 KB stage into ring slot (stage % DEPTH).
// Each lane copies 16 chunks of 16 B -> 512 B per cp.async "wavefront".
__device__ __forceinline__ void issue_stage(uint32_t sbase, const float* g,
                                            int stage, int t) {
    const int slot = stage % DEPTH;
    const float* src = g + stage * STAGE_FLOATS + t * 4;
    const uint32_t dst = sbase + slot * STAGE_BYTES + t * 16;
#pragma unroll
    for (int i = 0; i < 16; i++)
        cpa16(dst + i * 512, src + i * 128);
    cp_commit();
}

// Forward scalar MPS chain (one warp). Ring prologue (stages 0..DEPTH-1)
// must already be issued. Every iteration commits exactly one group
// (real or empty) so wait_group 4 always releases exactly stage m.
__device__ __forceinline__ float chain_fwd(
    const float* __restrict__ gmid, const float* __restrict__ first,
    const float* __restrict__ last, const float* sc, const float* ss,
    float* vbuf, const float* stg, uint32_t sbase, int t)
{
    vbuf[t] = fmaf(first[t], sc[0], first[32 + t] * ss[0]);
    __syncwarp();

#pragma unroll 1
    for (int m = 0; m < 25; m++) {
        cp_wait4();
        __syncwarp();                         // cross-lane visibility of stage m
        const float* __restrict__ A = stg + (m % DEPTH) * STAGE_FLOATS;
        const float c = sc[m + 1], sn = ss[m + 1];
        float acc = 0.0f;
#pragma unroll
        for (int d = 0; d < 32; d++)
            acc = fmaf(vbuf[d], fmaf(A[d * 64 + t], c, A[d * 64 + 32 + t] * sn), acc);
        __syncwarp();                         // all lanes done reading slot + vbuf
        vbuf[t] = acc;
        if (m + DEPTH < 25) issue_stage(sbase, gmid, m + DEPTH, t);
        else                cp_commit();      // empty group keeps wait_group math exact
        __syncwarp();
    }
    const float pv = vbuf[t] * fmaf(last[2 * t], sc[26], last[2 * t + 1] * ss[26]);
    return warp_sum(pv);
}

__global__ void reset_kernel() {
    if (threadIdx.x < 27) g_grp[threadIdx.x] = 0;
    if (threadIdx.x == 27) g_ctr1 = 0;
}

// Persistent fused kernel: 729 blocks x 32 threads, one wave.
// Blocks 0-26 additionally run layer 1; block 0 additionally runs the final layer.
__global__ void __launch_bounds__(32)
fused_kernel(const float* __restrict__ img,
             const float* __restrict__ l0f, const float* __restrict__ l0m,
             const float* __restrict__ l0l,
             const float* __restrict__ l1f, const float* __restrict__ l1m,
             const float* __restrict__ l1l,
             const float* __restrict__ ff,  const float* __restrict__ fm,
             const float* __restrict__ fl,
             float* __restrict__ out)
{
    extern __shared__ float stg[];                  // DEPTH x 2048 floats
    __shared__ float sc[27], ss[27], vbuf[32];

    const int n = blockIdx.x;
    const int t = threadIdx.x;
    const uint32_t sbase = smem_u32(stg);

    // ---------- Layer 0 ----------
    const float* gm0 = l0m + (long)n * (25 * STAGE_FLOATS);
#pragma unroll
    for (int s = 0; s < DEPTH; s++) issue_stage(sbase, gm0, s, t);

    if (t < 27) {
        const int bh = n / 81, bv = (n / 9) % 9, bd = n % 9;
        const int x = t / 9, y = (t / 3) % 3, z = t % 3;
        const float val = img[(3 * bh + x) * 729 + (3 * bv + y) * 27 + (3 * bd + z)];
        float cv, sv;
        sincosf(PI_HALF * val, &sv, &cv);
        sc[t] = cv; ss[t] = sv;
    }
    __syncwarp();

    float r = chain_fwd(gm0, l0f + n * 64, l0l + n * 64, sc, ss, vbuf, stg, sbase, t);
    if (t == 0) {
        g_out0[n] = r;
        __threadfence();
        // this block feeds exactly one layer-1 chain:
        const int X = n / 81, Y = (n / 9) % 9, Z = n % 9;
        atomicAdd(&g_grp[(X / 3) * 9 + (Y / 3) * 3 + (Z / 3)], 1u);
    }
    if (n >= 27) return;

    // ---------- Layer 1 (blocks 0..26) ----------
    const float* gm1 = l1m + n * (25 * STAGE_FLOATS);
    // Prefetch weights BEFORE spinning: ring prologue + L2 warm of the rest.
#pragma unroll
    for (int s = 0; s < DEPTH; s++) issue_stage(sbase, gm1, s, t);
    {
        const float* pf = gm1 + DEPTH * STAGE_FLOATS;     // remaining 20 stages = 160 KB
        for (int i = t; i < 20 * STAGE_FLOATS / 32; i += 32)
            l2_prefetch_line(pf + i * 32);
    }
    if (n == 0) {                                          // final-layer weights too
        for (int i = t; i < 25 * STAGE_FLOATS / 32; i += 32)
            l2_prefetch_line(fm + i * 32);
    }
    spin_until(&g_grp[n], 27u);                            // only my 27 producers

    if (t < 27) {
        const int bh = n / 9, bv = (n / 3) % 3, bd = n % 3;
        const int x = t / 9, y = (t / 3) % 3, z = t % 3;
        const float val = __ldcg(&g_out0[(3 * bh + x) * 81 + (3 * bv + y) * 9 + (3 * bd + z)]);
        float cv, sv;
        sincosf(PI_HALF * val, &sv, &cv);
        sc[t] = cv; ss[t] = sv;
    }
    __syncwarp();

    r = chain_fwd(gm1, l1f + n * 64, l1l + n * 64, sc, ss, vbuf, stg, sbase, t);
    if (t == 0) {
        g_out1[n] = r;
        __threadfence();
        atomicAdd(&g_ctr1, 1u);
    }
    if (n != 0) return;

    // ---------- Final layer (block 0): right-to-left, output leg at the end ----------
    // Prologue (reverse order) before spinning.
#pragma unroll
    for (int j = 0; j < DEPTH; j++) issue_stage(sbase, fm, 24 - j, t);
    spin_until(&g_ctr1, 27u);

    if (t < 27) {
        // (3,3,3) squeeze of g_out1 is the identity permutation
        float cv, sv;
        sincosf(PI_HALF * __ldcg(&g_out1[t]), &sv, &cv);
        sc[t] = cv; ss[t] = sv;
    }
    __syncwarp();

    // u_25[d] = last[d,0]*c26 + last[d,1]*s26
    vbuf[t] = fmaf(fl[2 * t], sc[26], fl[2 * t + 1] * ss[26]);
    __syncwarp();

#pragma unroll 1
    for (int j = 0; j < 25; j++) {
        const int stage = 24 - j;
        cp_wait4();
        __syncwarp();
        const float* __restrict__ A = stg + (stage % DEPTH) * STAGE_FLOATS;
        const float c = sc[stage + 1], sn = ss[stage + 1];
        float a0 = 0.0f, a1 = 0.0f;
        // u_new[t] = c*(A[t,0,:]·u) + s*(A[t,1,:]·u); rotated e keeps LDS conflict-free
#pragma unroll
        for (int k = 0; k < 32; k++) {
            const int e = (k + t) & 31;
            const float ue = vbuf[e];
            a0 = fmaf(A[t * 64 + e], ue, a0);
            a1 = fmaf(A[t * 64 + 32 + e], ue, a1);
        }
        const float un = fmaf(a0, c, a1 * sn);
        __syncwarp();
        vbuf[t] = un;
        if (stage - DEPTH >= 0) issue_stage(sbase, fm, stage - DEPTH, t);
        else                    cp_commit();
        __syncwarp();
    }

    const float ut = vbuf[t];
#pragma unroll
    for (int o = 0; o < 10; o++) {
        float p = fmaf(ff[o * 32 + t], sc[0], ff[320 + o * 32 + t] * ss[0]) * ut;
        p = warp_sum(p);
        if (t == 0) out[o] = p;
    }
}

extern "C" void kernel_launch(void* const* d_in, const int* in_sizes, int n_in,
                              void* d_out, int out_size)
{
    const float* img      = (const float*)d_in[0];
    const float* l0_first = (const float*)d_in[1];
    const float* l0_mid   = (const float*)d_in[2];
    const float* l0_last  = (const float*)d_in[3];
    const float* l1_first = (const float*)d_in[4];
    const float* l1_mid   = (const float*)d_in[5];
    const float* l1_last  = (const float*)d_in[6];
    const float* f_first  = (const float*)d_in[7];
    const float* f_mid    = (const float*)d_in[8];
    const float* f_last   = (const float*)d_in[9];
    float* out = (float*)d_out;

    reset_kernel<<<1, 32>>>();
    fused_kernel<<<729, 32, SMEM_DYN>>>(img, l0_first, l0_mid, l0_last,
                                        l1_first, l1_mid, l1_last,
                                        f_first, f_mid, f_last, out);
}